// round 7
// baseline (speedup 1.0000x reference)
#include <cuda_runtime.h>
#include <cuda_bf16.h>
#include <math.h>
#include <stdint.h>

#define MAXN   25600
#define D_IN   1068
#define KPADX  1088
#define FDIM   768
#define G4     3072
#define NPE    200
#define MAXDOC 256

typedef unsigned long long ull;

// ---------------- scratch (static device arrays; no allocations) ----------------
__device__ float SC_PE  [NPE * D_IN];
__device__ int   SC_POS [MAXN];
__device__ float SC_WT  [15 * 256 * D_IN];            // taps: 0..2 (k3), 3..7 (k5), 8..14 (k7)
__device__ float SC_FEAT[(size_t)MAXN * FDIM];
__device__ float SC_G   [(size_t)MAXN * G4];
__device__ float SC_CS  [(size_t)MAXN * FDIM];
__device__ float SC_H16 [2][16 * FDIM];
__device__ unsigned SC_ARRIVE;
__device__ unsigned SC_RELEASE;

// bf16 split planes (hi + lo), 16B aligned for cp.async
__device__ __align__(16) __nv_bfloat16 XBh[(size_t)MAXN * KPADX], XBl[(size_t)MAXN * KPADX];
__device__ __align__(16) __nv_bfloat16 WTBh[(size_t)3840 * KPADX], WTBl[(size_t)3840 * KPADX];
__device__ __align__(16) __nv_bfloat16 FBh[(size_t)MAXN * FDIM], FBl[(size_t)MAXN * FDIM];
__device__ __align__(16) __nv_bfloat16 PBh[(size_t)MAXN * FDIM], PBl[(size_t)MAXN * FDIM];
__device__ __align__(16) __nv_bfloat16 HBh[(size_t)MAXN * FDIM], HBl[(size_t)MAXN * FDIM];

// gate weights in mma-fragment order: idx = ((slot*384 + n8)*48 + k16)*32 + lane -> (b0|b1)
#define NFRAG (4 * 384 * 48 * 32)
__device__ __align__(16) ull WFH[NFRAG], WFL[NFRAG];

__device__ __forceinline__ float sigm(float x) { return 1.0f / (1.0f + expf(-x)); }

// ---- packed f32x2 helpers (scan) ----
__device__ __forceinline__ void ffma2(ull& d, ull a, ull b) {
    asm("fma.rn.f32x2 %0, %1, %2, %0;" : "+l"(d) : "l"(a), "l"(b));
}
__device__ __forceinline__ float2 up2(ull v) {
    float2 r; asm("mov.b64 {%0, %1}, %2;" : "=f"(r.x), "=f"(r.y) : "l"(v)); return r;
}

// ---- mma.sync / ldmatrix / cp.async (base PTX, compute_103-safe) ----
__device__ __forceinline__ uint32_t smem_u32(const void* p) {
    uint32_t a;
    asm("{ .reg .u64 t; cvta.to.shared.u64 t, %1; cvt.u32.u64 %0, t; }" : "=r"(a) : "l"(p));
    return a;
}
__device__ __forceinline__ void ldsm4(uint32_t* r, uint32_t addr) {
    asm volatile("ldmatrix.sync.aligned.m8n8.x4.shared.b16 {%0,%1,%2,%3}, [%4];"
        : "=r"(r[0]), "=r"(r[1]), "=r"(r[2]), "=r"(r[3]) : "r"(addr));
}
__device__ __forceinline__ void mma16816(float* c, const uint32_t* a, uint32_t b0, uint32_t b1) {
    asm volatile("mma.sync.aligned.m16n8k16.row.col.f32.bf16.bf16.f32 "
        "{%0,%1,%2,%3}, {%4,%5,%6,%7}, {%8,%9}, {%0,%1,%2,%3};"
        : "+f"(c[0]), "+f"(c[1]), "+f"(c[2]), "+f"(c[3])
        : "r"(a[0]), "r"(a[1]), "r"(a[2]), "r"(a[3]), "r"(b0), "r"(b1));
}
__device__ __forceinline__ void cpa16(uint32_t dst, const void* src, int valid) {
    asm volatile("cp.async.cg.shared.global [%0], [%1], 16, %2;"
        :: "r"(dst), "l"(src), "r"(valid ? 16 : 0) : "memory");
}
#define CP_COMMIT() asm volatile("cp.async.commit_group;" ::: "memory")
#define CP_WAIT1()  asm volatile("cp.async.wait_group 1;" ::: "memory")
#define CP_WAIT0()  asm volatile("cp.async.wait_group 0;" ::: "memory")

#define RS     80
#define PLANE  10240
#define BUFB   40960            // conv: 4 planes
#define SMEM_CONV (2 * BUFB)
#define GBUF   20480            // gate: 2 planes (A hi/lo)
#define SMEM_GATE (2 * GBUF)

// load one 128x32 bf16 plane into smem (2 chunks of 16B per thread)
__device__ __forceinline__ void ldp(uint32_t sdst, const __nv_bfloat16* src, int ldk,
                                    int rowBase, int rowLim, int kcol, int tid) {
#pragma unroll
    for (int it = 0; it < 2; ++it) {
        int ch = tid + it * 256;
        int row = ch >> 2, c = ch & 3;
        int r = rowBase + row;
        int v = (r >= 0 && r < rowLim);
        const void* s = src + ((size_t)(v ? r : 0) * ldk + kcol + c * 8);
        cpa16(sdst + row * RS + c * 16, s, v);
    }
}

// conv wcompute: A + B both from smem planes (3 split combos), acc[2][8][4]
__device__ __forceinline__ void wcompute(uint32_t sbuf, int lane, int wm, int wn,
                                         float acc[2][8][4]) {
    int arow = wm * 32 + (lane & 15);
    int brow = wn * 64 + (lane & 7) + ((lane >> 4) << 3);
#pragma unroll
    for (int kh = 0; kh < 2; ++kh) {
        int acol = kh * 16 + ((lane >> 4) << 3);
        int bcol = kh * 16 + (((lane >> 3) & 1) << 3);
        uint32_t ah[2][4], al[2][4];
#pragma unroll
        for (int mt = 0; mt < 2; ++mt) {
            uint32_t ad = sbuf + (arow + mt * 16) * RS + acol * 2;
            ldsm4(ah[mt], ad);
            ldsm4(al[mt], ad + PLANE);
        }
#pragma unroll
        for (int g = 0; g < 4; ++g) {
            uint32_t bh[4], bl[4];
            uint32_t bd = sbuf + 2 * PLANE + (brow + g * 16) * RS + bcol * 2;
            ldsm4(bh, bd);
            ldsm4(bl, bd + PLANE);
#pragma unroll
            for (int mt = 0; mt < 2; ++mt)
#pragma unroll
                for (int sub = 0; sub < 2; ++sub) {
                    int nt = g * 2 + sub;
                    mma16816(acc[mt][nt], ah[mt], bh[sub * 2], bh[sub * 2 + 1]);
                    mma16816(acc[mt][nt], ah[mt], bl[sub * 2], bl[sub * 2 + 1]);
                    mma16816(acc[mt][nt], al[mt], bh[sub * 2], bh[sub * 2 + 1]);
                }
        }
    }
}

// gate wcompute: A from smem, B fragments direct from L2 (WFH/WFL)
__device__ __forceinline__ void wcompute_g(uint32_t sbuf, int lane, int wm,
                                           int fragBase, float acc[2][8][4]) {
    int arow = wm * 32 + (lane & 15);
#pragma unroll
    for (int kh = 0; kh < 2; ++kh) {
        int acol = kh * 16 + ((lane >> 4) << 3);
        uint32_t ah[2][4], al[2][4];
#pragma unroll
        for (int mt = 0; mt < 2; ++mt) {
            uint32_t ad = sbuf + (arow + mt * 16) * RS + acol * 2;
            ldsm4(ah[mt], ad);
            ldsm4(al[mt], ad + PLANE);
        }
        int fb = fragBase + kh * 32 + lane;       // k16 stride = 32
#pragma unroll
        for (int g = 0; g < 4; ++g) {
#pragma unroll
            for (int sub = 0; sub < 2; ++sub) {
                int f = fb + (g * 2 + sub) * 1536;  // n8 stride = 48*32
                ull vh = __ldg(&WFH[f]);
                ull vl = __ldg(&WFL[f]);
                uint32_t bh0 = (uint32_t)vh, bh1 = (uint32_t)(vh >> 32);
                uint32_t bl0 = (uint32_t)vl, bl1 = (uint32_t)(vl >> 32);
                int nt = g * 2 + sub;
#pragma unroll
                for (int mt = 0; mt < 2; ++mt) {
                    mma16816(acc[mt][nt], ah[mt], bh0, bh1);
                    mma16816(acc[mt][nt], ah[mt], bl0, bl1);
                    mma16816(acc[mt][nt], al[mt], bh0, bh1);
                }
            }
        }
    }
}

// ---------------- fused prep: PE + posidx + conv weight transpose ----------------
__global__ void k_prep(const int* __restrict__ dl, int ndocs, int N,
                       const float* __restrict__ w0, const float* __restrict__ w1,
                       const float* __restrict__ w2) {
    int idx = blockIdx.x * blockDim.x + threadIdx.x;
    if (idx < NPE * D_IN) {
        int pos = idx / D_IN, ch = idx % D_IN;
        int i = ch >> 1;
        float e = (2.0f * (float)i) / (float)D_IN;
        float ang = (float)pos / powf(10000.0f, e);
        SC_PE[idx] = (ch & 1) ? cosf(ang) : sinf(ang);
    }
    const int per = 256 * D_IN;
    if (idx < 15 * per) {
        int t  = idx / per;
        int r  = idx - t * per;
        int oc = r / D_IN;
        int c  = r - oc * D_IN;
        const float* w; int ksz, tl;
        if (t < 3)      { w = w0; ksz = 3; tl = t; }
        else if (t < 8) { w = w1; ksz = 5; tl = t - 3; }
        else            { w = w2; ksz = 7; tl = t - 8; }
        SC_WT[idx] = w[((size_t)oc * D_IN + c) * ksz + tl];
    }
    if (blockIdx.x == 0) {
        __shared__ int off[MAXDOC + 1];
        if (threadIdx.x == 0) {
            int s = 0;
            for (int d = 0; d < ndocs; ++d) { off[d] = s; s += dl[d]; }
            off[ndocs] = s;
        }
        __syncthreads();
        for (int n = threadIdx.x; n < N; n += blockDim.x) {
            int lo = 0, hi = ndocs;
            while (hi - lo > 1) { int mid = (lo + hi) >> 1; if (off[mid] <= n) lo = mid; else hi = mid; }
            SC_POS[n] = n - off[lo];
        }
    }
}

// ---------------- fused: x + PE -> bf16 hi/lo planes ----------------
__global__ void k_addpe_cvt(const float* __restrict__ x, int N) {
    long long idx = (long long)blockIdx.x * blockDim.x + threadIdx.x;
    long long tot = (long long)N * KPADX;
    if (idx >= tot) return;
    int n = (int)(idx / KPADX), k = (int)(idx % KPADX);
    float v = 0.f;
    if (k < D_IN) v = x[(size_t)n * D_IN + k] + SC_PE[SC_POS[n] * D_IN + k];
    __nv_bfloat16 h = __float2bfloat16(v);
    XBh[idx] = h;
    XBl[idx] = __float2bfloat16(v - __bfloat162float(h));
}

// ---------------- fused weight conversions: WT planes + gate fragments + reset ----------------
__global__ void k_wcvt(const float* __restrict__ s0, const float* __restrict__ s1,
                       const float* __restrict__ s2, const float* __restrict__ s3) {
    long long idx = (long long)blockIdx.x * blockDim.x + threadIdx.x;
    // conv weight planes: 3840 x KPADX
    if (idx < (long long)3840 * KPADX) {
        int r = (int)(idx / KPADX), k = (int)(idx % KPADX);
        float v = (k < D_IN) ? SC_WT[(size_t)r * D_IN + k] : 0.f;
        __nv_bfloat16 h = __float2bfloat16(v);
        WTBh[idx] = h;
        WTBl[idx] = __float2bfloat16(v - __bfloat162float(h));
    }
    // gate weight fragments
    if (idx < NFRAG) {
        int lane = (int)(idx & 31);
        int t = (int)(idx >> 5);
        int k16 = t % 48; t /= 48;
        int n8 = t % 384;
        int slot = t / 384;
        const float* W = (slot == 0) ? s0 : (slot == 1) ? s1 : (slot == 2) ? s2 : s3;
        const float* wr = W + (size_t)(n8 * 8 + (lane >> 2)) * FDIM + k16 * 16 + (lane & 3) * 2;
        float w0 = wr[0], w1 = wr[1], w8 = wr[8], w9 = wr[9];
        __nv_bfloat16 h0 = __float2bfloat16(w0), h1 = __float2bfloat16(w1);
        __nv_bfloat16 h8 = __float2bfloat16(w8), h9 = __float2bfloat16(w9);
        uint32_t b0h = ((uint32_t)__bfloat16_as_ushort(h1) << 16) | __bfloat16_as_ushort(h0);
        uint32_t b1h = ((uint32_t)__bfloat16_as_ushort(h9) << 16) | __bfloat16_as_ushort(h8);
        WFH[idx] = (ull)b0h | ((ull)b1h << 32);
        __nv_bfloat16 l0 = __float2bfloat16(w0 - __bfloat162float(h0));
        __nv_bfloat16 l1 = __float2bfloat16(w1 - __bfloat162float(h1));
        __nv_bfloat16 l8 = __float2bfloat16(w8 - __bfloat162float(h8));
        __nv_bfloat16 l9 = __float2bfloat16(w9 - __bfloat162float(h9));
        uint32_t b0l = ((uint32_t)__bfloat16_as_ushort(l1) << 16) | __bfloat16_as_ushort(l0);
        uint32_t b1l = ((uint32_t)__bfloat16_as_ushort(l9) << 16) | __bfloat16_as_ushort(l8);
        WFL[idx] = (ull)b0l | ((ull)b1l << 32);
    }
    // scan state reset
    if (idx == 0) { SC_ARRIVE = 0u; SC_RELEASE = 0u; }
    if (idx < 16 * FDIM) SC_H16[0][idx] = 0.f;
}

// ---------------- mma conv (unchanged structure) ----------------
__global__ __launch_bounds__(256, 2)
void k_mmconv(int ksz, int tapBase, int ocBase, const float* __restrict__ bias, int N) {
    extern __shared__ char smem[];
    uint32_t sb = smem_u32(smem);
    int tid = threadIdx.x, lane = tid & 31, wid = tid >> 5;
    int wm = wid & 3, wn = wid >> 2;
    int m0 = blockIdx.x * 128, n0 = blockIdx.y * 128;
    int pad = ksz >> 1;
    int nblk = ksz * 34;
    float acc[2][8][4] = {};

    auto load_blk = [&](int i) {
        int buf = i & 1;
        int p = i / 34, kb = i - p * 34;
        int sh = p - pad;
        uint32_t bb = sb + buf * BUFB;
        const __nv_bfloat16* wth = WTBh + (size_t)(tapBase + p) * 256 * KPADX;
        const __nv_bfloat16* wtl = WTBl + (size_t)(tapBase + p) * 256 * KPADX;
        ldp(bb,             XBh, KPADX, m0 + sh, N,   kb * 32, tid);
        ldp(bb + PLANE,     XBl, KPADX, m0 + sh, N,   kb * 32, tid);
        ldp(bb + 2 * PLANE, wth, KPADX, n0,      256, kb * 32, tid);
        ldp(bb + 3 * PLANE, wtl, KPADX, n0,      256, kb * 32, tid);
        CP_COMMIT();
    };

    load_blk(0);
    for (int i = 0; i < nblk; ++i) {
        if (i + 1 < nblk) { load_blk(i + 1); CP_WAIT1(); } else { CP_WAIT0(); }
        __syncthreads();
        wcompute(sb + (i & 1) * BUFB, lane, wm, wn, acc);
        __syncthreads();
    }

#pragma unroll
    for (int mt = 0; mt < 2; ++mt)
#pragma unroll
        for (int nt = 0; nt < 8; ++nt) {
            int col = n0 + wn * 64 + nt * 8 + (lane & 3) * 2;
            float b0 = bias[col], b1 = bias[col + 1];
            int r0 = m0 + wm * 32 + mt * 16 + (lane >> 2);
#pragma unroll
            for (int hh = 0; hh < 2; ++hh) {
                int m = r0 + hh * 8;
                if (m < N) {
                    float v0 = acc[mt][nt][hh * 2]     + b0;
                    float v1 = acc[mt][nt][hh * 2 + 1] + b1;
                    v0 = (v0 >= 0.f) ? v0 : 0.01f * v0;
                    v1 = (v1 >= 0.f) ? v1 : 0.01f * v1;
                    SC_FEAT[(size_t)m * FDIM + ocBase + col]     = v0;
                    SC_FEAT[(size_t)m * FDIM + ocBase + col + 1] = v1;
                }
            }
        }
}

// ---------------- gate GEMM v2: A via smem, B fragments via L2 ----------------
// SC_G = A1@W[slot1]^T [+ A2(shift)@W[slot2]^T] + b1 + b2
__global__ __launch_bounds__(256, 2)
void k_mmgate(int aSel, int slot1, int pass2, int slot2, int shift2,
              const float* __restrict__ b1, const float* __restrict__ b2, int N) {
    extern __shared__ char smem[];
    uint32_t sb = smem_u32(smem);
    int tid = threadIdx.x, lane = tid & 31, wid = tid >> 5;
    int wm = wid & 3, wn = wid >> 2;
    int m0 = blockIdx.x * 128, n0 = blockIdx.y * 128;
    int nblk = pass2 ? 48 : 24;
    int nb8 = (n0 >> 3) + wn * 8;
    float acc[2][8][4] = {};

    auto load_blk = [&](int i) {
        int buf = i & 1;
        int p = i / 24, kb = i - p * 24;
        const __nv_bfloat16 *ah, *al;
        int sh;
        if (p == 0) { ah = aSel ? FBh : PBh; al = aSel ? FBl : PBl; sh = 0; }
        else        { ah = HBh; al = HBl; sh = shift2; }
        uint32_t bb = sb + buf * GBUF;
        ldp(bb,         ah, FDIM, m0 + sh, N, kb * 32, tid);
        ldp(bb + PLANE, al, FDIM, m0 + sh, N, kb * 32, tid);
        CP_COMMIT();
    };

    load_blk(0);
    for (int i = 0; i < nblk; ++i) {
        if (i + 1 < nblk) { load_blk(i + 1); CP_WAIT1(); } else { CP_WAIT0(); }
        __syncthreads();
        int p = i / 24, kb = i - p * 24;
        int slot = p ? slot2 : slot1;
        int fragBase = ((slot * 384 + nb8) * 48 + kb * 2) * 32;
        wcompute_g(sb + (i & 1) * GBUF, lane, wm, fragBase, acc);
        __syncthreads();
    }

#pragma unroll
    for (int mt = 0; mt < 2; ++mt)
#pragma unroll
        for (int nt = 0; nt < 8; ++nt) {
            int g = n0 + wn * 64 + nt * 8 + (lane & 3) * 2;
            float bv0 = b1[g] + b2[g];
            float bv1 = b1[g + 1] + b2[g + 1];
            int r0 = m0 + wm * 32 + mt * 16 + (lane >> 2);
#pragma unroll
            for (int hh = 0; hh < 2; ++hh) {
                int m = r0 + hh * 8;
                if (m < N) {
                    SC_G[(size_t)m * G4 + g]     = acc[mt][nt][hh * 2]     + bv0;
                    SC_G[(size_t)m * G4 + g + 1] = acc[mt][nt][hh * 2 + 1] + bv1;
                }
            }
        }
}

// ---------------- fused: FEAT -> FB planes; maxpool -> PB planes ----------------
__global__ void k_postconv(int N) {
    long long idx = (long long)blockIdx.x * blockDim.x + threadIdx.x;
    long long tot = (long long)N * FDIM;
    if (idx >= tot) return;
    int n = (int)(idx / FDIM), ch = (int)(idx % FDIM);
    float f = SC_FEAT[idx];
    __nv_bfloat16 fh = __float2bfloat16(f);
    FBh[idx] = fh;
    FBl[idx] = __float2bfloat16(f - __bfloat162float(fh));
    int ksz = 3 + 2 * (ch >> 8);
    int p = ksz >> 1;
    float m = f;
    for (int d = -p; d <= p; ++d) {
        int nn = n + d;
        if (d != 0 && nn >= 0 && nn < N) m = fmaxf(m, SC_FEAT[(long long)nn * FDIM + ch]);
    }
    __nv_bfloat16 mh = __float2bfloat16(m);
    PBh[idx] = mh;
    PBl[idx] = __float2bfloat16(m - __bfloat162float(mh));
}

// ---------------- persistent chunked-LSTM scan ----------------
__global__ void k_scan(const float* __restrict__ Whh, int N, int nChunks) {
    __shared__ float4 sh4[16 * 192];
    float* shp = (float*)sh4;
    int t = threadIdx.x, b = blockIdx.x;
    int j = t & 15;
    int q = t >> 4;
    int hl = q % 6, gate = q / 6;
    int h_idx = b * 6 + hl;
    int grow = gate * FDIM + h_idx;
    const float4* w4 = (const float4*)(Whh + (long long)grow * FDIM);
    float c_reg = 0.f;

    for (int s = 0; s < nChunks; ++s) {
        const float4* src = (const float4*)(SC_H16[s & 1]);
        for (int f = t; f < 3072; f += 384) {
            float4 v = __ldcg(src + f);
            int jj = f / 192, k4 = f - jj * 192;
            sh4[jj * 192 + (k4 ^ jj)] = v;
        }
        __syncthreads();

        int pos = s * 16 + j;
        float pre = 0.f;
        if (pos < N) {
            const float4* h4 = sh4 + j * 192;
            ull acc0 = 0, acc1 = 0;
#pragma unroll 4
            for (int k4 = 0; k4 < 192; ++k4) {
                float4 w = __ldg(w4 + k4);
                float4 h = h4[k4 ^ j];
                ull wlo, whi, hlo, hhi;
                asm("mov.b64 %0, {%1, %2};" : "=l"(wlo) : "f"(w.x), "f"(w.y));
                asm("mov.b64 %0, {%1, %2};" : "=l"(whi) : "f"(w.z), "f"(w.w));
                asm("mov.b64 %0, {%1, %2};" : "=l"(hlo) : "f"(h.x), "f"(h.y));
                asm("mov.b64 %0, {%1, %2};" : "=l"(hhi) : "f"(h.z), "f"(h.w));
                ffma2(acc0, wlo, hlo);
                ffma2(acc1, whi, hhi);
            }
            float2 s0 = up2(acc0), s1 = up2(acc1);
            pre = __ldg(&SC_G[(long long)pos * G4 + grow]) + ((s0.x + s0.y) + (s1.x + s1.y));
        }
        __syncthreads();
        shp[j * 24 + q] = pre;
        __syncthreads();

        if (q < 6 && pos < N) {
            float gi = shp[j * 24 + hl];
            float gf = shp[j * 24 + 6  + hl];
            float gg = shp[j * 24 + 12 + hl];
            float go = shp[j * 24 + 18 + hl];
            float c2 = sigm(gf) * c_reg + sigm(gi) * tanhf(gg);
            float h2 = sigm(go) * tanhf(c2);
            c_reg = c2;
            long long o = (long long)pos * FDIM + h_idx;
            SC_CS[o] = c2;
            __nv_bfloat16 hh = __float2bfloat16(h2);
            HBh[o] = hh;
            HBl[o] = __float2bfloat16(h2 - __bfloat162float(hh));
            SC_H16[(s + 1) & 1][j * FDIM + h_idx] = h2;
        }

        __threadfence();
        __syncthreads();
        if (t == 0) {
            unsigned prev = atomicAdd(&SC_ARRIVE, 1u);
            unsigned target = (unsigned)(s + 1) * gridDim.x;
            if (prev + 1 == target) {
                atomicExch(&SC_RELEASE, (unsigned)(s + 1));
            } else {
                while (*(volatile unsigned*)&SC_RELEASE < (unsigned)(s + 1)) __nanosleep(32);
            }
            __threadfence();
        }
        __syncthreads();
    }
}

// ---------------- final LSTM-cell gate fuse ----------------
__global__ void k_final(float* __restrict__ out, int N, int shift, int outOff) {
    long long idx = (long long)blockIdx.x * blockDim.x + threadIdx.x;
    long long tot = (long long)N * FDIM;
    if (idx >= tot) return;
    int n = (int)(idx / FDIM), h = (int)(idx % FDIM);
    int ns = n + shift;
    float cin = (ns >= 0 && ns < N) ? SC_CS[(long long)ns * FDIM + h] : 0.f;
    const float* g = SC_G + (long long)n * G4;
    float gi = g[h], gf = g[FDIM + h], gg = g[2 * FDIM + h], go = g[3 * FDIM + h];
    float c2 = sigm(gf) * cin + sigm(gi) * tanhf(gg);
    out[(long long)n * 1536 + outOff + h] = sigm(go) * tanhf(c2);
}

// ---------------- launch ----------------
extern "C" void kernel_launch(void* const* d_in, const int* in_sizes, int n_in,
                              void* d_out, int out_size) {
    const float* x    = (const float*)d_in[0];
    const int*   dl   = (const int*)  d_in[1];
    const float* cw0  = (const float*)d_in[2];  const float* cb0 = (const float*)d_in[3];
    const float* cw1  = (const float*)d_in[4];  const float* cb1 = (const float*)d_in[5];
    const float* cw2  = (const float*)d_in[6];  const float* cb2 = (const float*)d_in[7];
    const float* Wih  = (const float*)d_in[8];  const float* Whh  = (const float*)d_in[9];
    const float* bih  = (const float*)d_in[10]; const float* bhh  = (const float*)d_in[11];
    const float* WihR = (const float*)d_in[12]; const float* WhhR = (const float*)d_in[13];
    const float* bihR = (const float*)d_in[14]; const float* bhhR = (const float*)d_in[15];
    float* out = (float*)d_out;

    int ndocs = in_sizes[1];
    int N = out_size / 1536;
    if (N > MAXN) N = MAXN;
    int nChunks = (N + 15) / 16;

    cudaFuncSetAttribute(k_mmconv, cudaFuncAttributeMaxDynamicSharedMemorySize, SMEM_CONV);
    cudaFuncSetAttribute(k_mmgate, cudaFuncAttributeMaxDynamicSharedMemorySize, SMEM_GATE);

    // 0: PE + posidx + conv weight transpose
    k_prep<<<(15 * 256 * D_IN + 255) / 256, 256>>>(dl, ndocs, N, cw0, cw1, cw2);
    // 1: x + PE -> XB planes
    {
        long long tot = (long long)N * KPADX;
        k_addpe_cvt<<<(int)((tot + 255) / 256), 256>>>(x, N);
    }
    // 2: all weight conversions + scan-state reset
    k_wcvt<<<(int)(((long long)3840 * KPADX + 255) / 256), 256>>>(Wih, Whh, WihR, WhhR);

    int mt = (N + 127) / 128;
    dim3 cg(mt, 2);
    // 3-5: convs (heavy; in the ncu capture window)
    k_mmconv<<<cg, 256, SMEM_CONV>>>(7, 8, 512, cb2, N);
    k_mmconv<<<cg, 256, SMEM_CONV>>>(5, 3, 256, cb1, N);
    k_mmconv<<<cg, 256, SMEM_CONV>>>(3, 0, 0,   cb0, N);

    // 6: pool + FB/PB planes
    {
        long long tot = (long long)N * FDIM;
        k_postconv<<<(int)((tot + 255) / 256), 256>>>(N);
    }

    dim3 gg(mt, G4 / 128);
    // 7: gx = pool @ Wih^T + b_ih + b_hh
    k_mmgate<<<gg, 256, SMEM_GATE>>>(0, 0, 0, 0, 0, bih, bhh, N);
    // 8: scan
    k_scan<<<128, 384>>>(Whh, N, nChunks);

    // 9-10: forward final cell
    k_mmgate<<<gg, 256, SMEM_GATE>>>(1, 0, 1, 1, -9, bih, bhh, N);
    {
        long long tot = (long long)N * FDIM;
        k_final<<<(int)((tot + 255) / 256), 256>>>(out, N, -9, 0);
    }
    // 11-12: reverse final cell
    k_mmgate<<<gg, 256, SMEM_GATE>>>(1, 2, 1, 3, 9, bihR, bhhR, N);
    {
        long long tot = (long long)N * FDIM;
        k_final<<<(int)((tot + 255) / 256), 256>>>(out, N, 9, 768);
    }
}

// round 8
// speedup vs baseline: 1.3736x; 1.3736x over previous
#include <cuda_runtime.h>
#include <cuda_bf16.h>
#include <math.h>
#include <stdint.h>

#define MAXN   25600
#define D_IN   1068
#define KPADX  1088
#define FDIM   768
#define G4     3072
#define NPE    200
#define MAXDOC 256

typedef unsigned long long ull;

// ---------------- scratch (static device arrays; no allocations) ----------------
__device__ float SC_PE  [NPE * D_IN];
__device__ int   SC_POS [MAXN];
__device__ float SC_WT  [15 * 256 * D_IN];            // taps: 0..2 (k3), 3..7 (k5), 8..14 (k7)
__device__ float SC_FEAT[(size_t)MAXN * FDIM];
__device__ float SC_G   [(size_t)MAXN * G4];
__device__ float SC_CS  [(size_t)MAXN * FDIM];
__device__ float SC_H16 [2][16 * FDIM];
__device__ unsigned SC_ARRIVE;
__device__ unsigned SC_RELEASE;

// bf16 split planes (hi + lo), 16B aligned for cp.async
__device__ __align__(16) __nv_bfloat16 XBh[(size_t)MAXN * KPADX], XBl[(size_t)MAXN * KPADX];
__device__ __align__(16) __nv_bfloat16 WTBh[(size_t)3840 * KPADX], WTBl[(size_t)3840 * KPADX];
__device__ __align__(16) __nv_bfloat16 FBh[(size_t)MAXN * FDIM], FBl[(size_t)MAXN * FDIM];
__device__ __align__(16) __nv_bfloat16 PBh[(size_t)MAXN * FDIM], PBl[(size_t)MAXN * FDIM];
__device__ __align__(16) __nv_bfloat16 HBh[(size_t)MAXN * FDIM], HBl[(size_t)MAXN * FDIM];
__device__ __align__(16) __nv_bfloat16 WGBh[(size_t)4 * G4 * FDIM], WGBl[(size_t)4 * G4 * FDIM];

__device__ __forceinline__ float sigm(float x) { return 1.0f / (1.0f + expf(-x)); }

// ---- packed f32x2 helpers (scan) ----
__device__ __forceinline__ void ffma2(ull& d, ull a, ull b) {
    asm("fma.rn.f32x2 %0, %1, %2, %0;" : "+l"(d) : "l"(a), "l"(b));
}
__device__ __forceinline__ float2 up2(ull v) {
    float2 r; asm("mov.b64 {%0, %1}, %2;" : "=f"(r.x), "=f"(r.y) : "l"(v)); return r;
}

// ---- mma.sync / ldmatrix / cp.async (base PTX, compute_103-safe) ----
__device__ __forceinline__ uint32_t smem_u32(const void* p) {
    uint32_t a;
    asm("{ .reg .u64 t; cvta.to.shared.u64 t, %1; cvt.u32.u64 %0, t; }" : "=r"(a) : "l"(p));
    return a;
}
__device__ __forceinline__ void ldsm4(uint32_t* r, uint32_t addr) {
    asm volatile("ldmatrix.sync.aligned.m8n8.x4.shared.b16 {%0,%1,%2,%3}, [%4];"
        : "=r"(r[0]), "=r"(r[1]), "=r"(r[2]), "=r"(r[3]) : "r"(addr));
}
__device__ __forceinline__ void mma16816(float* c, const uint32_t* a, uint32_t b0, uint32_t b1) {
    asm volatile("mma.sync.aligned.m16n8k16.row.col.f32.bf16.bf16.f32 "
        "{%0,%1,%2,%3}, {%4,%5,%6,%7}, {%8,%9}, {%0,%1,%2,%3};"
        : "+f"(c[0]), "+f"(c[1]), "+f"(c[2]), "+f"(c[3])
        : "r"(a[0]), "r"(a[1]), "r"(a[2]), "r"(a[3]), "r"(b0), "r"(b1));
}
__device__ __forceinline__ void cpa16(uint32_t dst, const void* src, int valid) {
    asm volatile("cp.async.cg.shared.global [%0], [%1], 16, %2;"
        :: "r"(dst), "l"(src), "r"(valid ? 16 : 0) : "memory");
}
#define CP_COMMIT() asm volatile("cp.async.commit_group;" ::: "memory")
#define CP_WAIT1()  asm volatile("cp.async.wait_group 1;" ::: "memory")
#define CP_WAIT0()  asm volatile("cp.async.wait_group 0;" ::: "memory")

#define RS     80
#define PLANE  10240
#define BUFB   40960
#define SMEM_MMA (2 * BUFB)

// load one 128x32 bf16 plane into smem (2 chunks of 16B per thread)
__device__ __forceinline__ void ldp(uint32_t sdst, const __nv_bfloat16* src, int ldk,
                                    int rowBase, int rowLim, int kcol, int tid) {
#pragma unroll
    for (int it = 0; it < 2; ++it) {
        int ch = tid + it * 256;
        int row = ch >> 2, c = ch & 3;
        int r = rowBase + row;
        int v = (r >= 0 && r < rowLim);
        const void* s = src + ((size_t)(v ? r : 0) * ldk + kcol + c * 8);
        cpa16(sdst + row * RS + c * 16, s, v);
    }
}

// per-warp compute on one 32-K block: 3 split combos, acc[2][8][4]
__device__ __forceinline__ void wcompute(uint32_t sbuf, int lane, int wm, int wn,
                                         float acc[2][8][4]) {
    int arow = wm * 32 + (lane & 15);
    int brow = wn * 64 + (lane & 7) + ((lane >> 4) << 3);
#pragma unroll
    for (int kh = 0; kh < 2; ++kh) {
        int acol = kh * 16 + ((lane >> 4) << 3);
        int bcol = kh * 16 + (((lane >> 3) & 1) << 3);
        uint32_t ah[2][4], al[2][4];
#pragma unroll
        for (int mt = 0; mt < 2; ++mt) {
            uint32_t ad = sbuf + (arow + mt * 16) * RS + acol * 2;
            ldsm4(ah[mt], ad);
            ldsm4(al[mt], ad + PLANE);
        }
#pragma unroll
        for (int g = 0; g < 4; ++g) {
            uint32_t bh[4], bl[4];
            uint32_t bd = sbuf + 2 * PLANE + (brow + g * 16) * RS + bcol * 2;
            ldsm4(bh, bd);
            ldsm4(bl, bd + PLANE);
#pragma unroll
            for (int mt = 0; mt < 2; ++mt)
#pragma unroll
                for (int sub = 0; sub < 2; ++sub) {
                    int nt = g * 2 + sub;
                    mma16816(acc[mt][nt], ah[mt], bh[sub * 2], bh[sub * 2 + 1]);
                    mma16816(acc[mt][nt], ah[mt], bl[sub * 2], bl[sub * 2 + 1]);
                    mma16816(acc[mt][nt], al[mt], bh[sub * 2], bh[sub * 2 + 1]);
                }
        }
    }
}

// ---------------- fused prep: PE + posidx + conv weight transpose ----------------
__global__ void k_prep(const int* __restrict__ dl, int ndocs, int N,
                       const float* __restrict__ w0, const float* __restrict__ w1,
                       const float* __restrict__ w2) {
    int idx = blockIdx.x * blockDim.x + threadIdx.x;
    if (idx < NPE * D_IN) {
        int pos = idx / D_IN, ch = idx % D_IN;
        int i = ch >> 1;
        float e = (2.0f * (float)i) / (float)D_IN;
        float ang = (float)pos / powf(10000.0f, e);
        SC_PE[idx] = (ch & 1) ? cosf(ang) : sinf(ang);
    }
    const int per = 256 * D_IN;
    if (idx < 15 * per) {
        int t  = idx / per;
        int r  = idx - t * per;
        int oc = r / D_IN;
        int c  = r - oc * D_IN;
        const float* w; int ksz, tl;
        if (t < 3)      { w = w0; ksz = 3; tl = t; }
        else if (t < 8) { w = w1; ksz = 5; tl = t - 3; }
        else            { w = w2; ksz = 7; tl = t - 8; }
        SC_WT[idx] = w[((size_t)oc * D_IN + c) * ksz + tl];
    }
    if (blockIdx.x == 0) {
        __shared__ int off[MAXDOC + 1];
        if (threadIdx.x == 0) {
            int s = 0;
            for (int d = 0; d < ndocs; ++d) { off[d] = s; s += dl[d]; }
            off[ndocs] = s;
        }
        __syncthreads();
        for (int n = threadIdx.x; n < N; n += blockDim.x) {
            int lo = 0, hi = ndocs;
            while (hi - lo > 1) { int mid = (lo + hi) >> 1; if (off[mid] <= n) lo = mid; else hi = mid; }
            SC_POS[n] = n - off[lo];
        }
    }
}

// ---------------- fused: x + PE -> bf16 hi/lo planes ----------------
__global__ void k_addpe_cvt(const float* __restrict__ x, int N) {
    long long idx = (long long)blockIdx.x * blockDim.x + threadIdx.x;
    long long tot = (long long)N * KPADX;
    if (idx >= tot) return;
    int n = (int)(idx / KPADX), k = (int)(idx % KPADX);
    float v = 0.f;
    if (k < D_IN) v = x[(size_t)n * D_IN + k] + SC_PE[SC_POS[n] * D_IN + k];
    __nv_bfloat16 h = __float2bfloat16(v);
    XBh[idx] = h;
    XBl[idx] = __float2bfloat16(v - __bfloat162float(h));
}

// ---------------- fused weight conversions: WT planes + gate weight planes + reset ----------------
__global__ void k_wcvt(const float* __restrict__ s0, const float* __restrict__ s1,
                       const float* __restrict__ s2, const float* __restrict__ s3) {
    long long idx = (long long)blockIdx.x * blockDim.x + threadIdx.x;
    // conv weight planes: 3840 x KPADX
    if (idx < (long long)3840 * KPADX) {
        int r = (int)(idx / KPADX), k = (int)(idx % KPADX);
        float v = (k < D_IN) ? SC_WT[(size_t)r * D_IN + k] : 0.f;
        __nv_bfloat16 h = __float2bfloat16(v);
        WTBh[idx] = h;
        WTBl[idx] = __float2bfloat16(v - __bfloat162float(h));
    }
    // gate weight planes: 4 slots x G4 x FDIM
    const long long per = (long long)G4 * FDIM;
    if (idx < 4 * per) {
        int slot = (int)(idx / per);
        long long r = idx - (long long)slot * per;
        const float* s = (slot == 0) ? s0 : (slot == 1) ? s1 : (slot == 2) ? s2 : s3;
        float v = s[r];
        __nv_bfloat16 h = __float2bfloat16(v);
        WGBh[idx] = h;
        WGBl[idx] = __float2bfloat16(v - __bfloat162float(h));
    }
    // scan state reset
    if (idx == 0) { SC_ARRIVE = 0u; SC_RELEASE = 0u; }
    if (idx < 16 * FDIM) SC_H16[0][idx] = 0.f;
}

// ---------------- mma conv ----------------
__global__ __launch_bounds__(256, 2)
void k_mmconv(int ksz, int tapBase, int ocBase, const float* __restrict__ bias, int N) {
    extern __shared__ char smem[];
    uint32_t sb = smem_u32(smem);
    int tid = threadIdx.x, lane = tid & 31, wid = tid >> 5;
    int wm = wid & 3, wn = wid >> 2;
    int m0 = blockIdx.x * 128, n0 = blockIdx.y * 128;
    int pad = ksz >> 1;
    int nblk = ksz * 34;
    float acc[2][8][4] = {};

    auto load_blk = [&](int i) {
        int buf = i & 1;
        int p = i / 34, kb = i - p * 34;
        int sh = p - pad;
        uint32_t bb = sb + buf * BUFB;
        const __nv_bfloat16* wth = WTBh + (size_t)(tapBase + p) * 256 * KPADX;
        const __nv_bfloat16* wtl = WTBl + (size_t)(tapBase + p) * 256 * KPADX;
        ldp(bb,             XBh, KPADX, m0 + sh, N,   kb * 32, tid);
        ldp(bb + PLANE,     XBl, KPADX, m0 + sh, N,   kb * 32, tid);
        ldp(bb + 2 * PLANE, wth, KPADX, n0,      256, kb * 32, tid);
        ldp(bb + 3 * PLANE, wtl, KPADX, n0,      256, kb * 32, tid);
        CP_COMMIT();
    };

    load_blk(0);
    for (int i = 0; i < nblk; ++i) {
        if (i + 1 < nblk) { load_blk(i + 1); CP_WAIT1(); } else { CP_WAIT0(); }
        __syncthreads();
        wcompute(sb + (i & 1) * BUFB, lane, wm, wn, acc);
        __syncthreads();
    }

#pragma unroll
    for (int mt = 0; mt < 2; ++mt)
#pragma unroll
        for (int nt = 0; nt < 8; ++nt) {
            int col = n0 + wn * 64 + nt * 8 + (lane & 3) * 2;
            float b0 = bias[col], b1 = bias[col + 1];
            int r0 = m0 + wm * 32 + mt * 16 + (lane >> 2);
#pragma unroll
            for (int hh = 0; hh < 2; ++hh) {
                int m = r0 + hh * 8;
                if (m < N) {
                    float v0 = acc[mt][nt][hh * 2]     + b0;
                    float v1 = acc[mt][nt][hh * 2 + 1] + b1;
                    v0 = (v0 >= 0.f) ? v0 : 0.01f * v0;
                    v1 = (v1 >= 0.f) ? v1 : 0.01f * v1;
                    SC_FEAT[(size_t)m * FDIM + ocBase + col]     = v0;
                    SC_FEAT[(size_t)m * FDIM + ocBase + col + 1] = v1;
                }
            }
        }
}

// ---------------- gate GEMM (round-5 form): SC_G = A1@B1^T [+ A2(shift)@B2^T] + b1 + b2 ----------------
__global__ __launch_bounds__(256, 2)
void k_mmgate(int aSel, int wSlot, int pass2, int wSlot2, int shift2,
              const float* __restrict__ b1, const float* __restrict__ b2, int N) {
    extern __shared__ char smem[];
    uint32_t sb = smem_u32(smem);
    int tid = threadIdx.x, lane = tid & 31, wid = tid >> 5;
    int wm = wid & 3, wn = wid >> 2;
    int m0 = blockIdx.x * 128, n0 = blockIdx.y * 128;
    int nblk = pass2 ? 48 : 24;
    float acc[2][8][4] = {};

    auto load_blk = [&](int i) {
        int buf = i & 1;
        int p = i / 24, kb = i - p * 24;
        const __nv_bfloat16 *ah, *al, *bh, *bl;
        int sh;
        if (p == 0) {
            ah = aSel ? FBh : PBh; al = aSel ? FBl : PBl;
            bh = WGBh + (size_t)wSlot * G4 * FDIM;
            bl = WGBl + (size_t)wSlot * G4 * FDIM;
            sh = 0;
        } else {
            ah = HBh; al = HBl;
            bh = WGBh + (size_t)wSlot2 * G4 * FDIM;
            bl = WGBl + (size_t)wSlot2 * G4 * FDIM;
            sh = shift2;
        }
        uint32_t bb = sb + buf * BUFB;
        ldp(bb,             ah, FDIM, m0 + sh, N,  kb * 32, tid);
        ldp(bb + PLANE,     al, FDIM, m0 + sh, N,  kb * 32, tid);
        ldp(bb + 2 * PLANE, bh, FDIM, n0,      G4, kb * 32, tid);
        ldp(bb + 3 * PLANE, bl, FDIM, n0,      G4, kb * 32, tid);
        CP_COMMIT();
    };

    load_blk(0);
    for (int i = 0; i < nblk; ++i) {
        if (i + 1 < nblk) { load_blk(i + 1); CP_WAIT1(); } else { CP_WAIT0(); }
        __syncthreads();
        wcompute(sb + (i & 1) * BUFB, lane, wm, wn, acc);
        __syncthreads();
    }

#pragma unroll
    for (int mt = 0; mt < 2; ++mt)
#pragma unroll
        for (int nt = 0; nt < 8; ++nt) {
            int g = n0 + wn * 64 + nt * 8 + (lane & 3) * 2;
            float bv0 = b1[g] + b2[g];
            float bv1 = b1[g + 1] + b2[g + 1];
            int r0 = m0 + wm * 32 + mt * 16 + (lane >> 2);
#pragma unroll
            for (int hh = 0; hh < 2; ++hh) {
                int m = r0 + hh * 8;
                if (m < N) {
                    SC_G[(size_t)m * G4 + g]     = acc[mt][nt][hh * 2]     + bv0;
                    SC_G[(size_t)m * G4 + g + 1] = acc[mt][nt][hh * 2 + 1] + bv1;
                }
            }
        }
}

// ---------------- fused: FEAT -> FB planes; maxpool -> PB planes ----------------
__global__ void k_postconv(int N) {
    long long idx = (long long)blockIdx.x * blockDim.x + threadIdx.x;
    long long tot = (long long)N * FDIM;
    if (idx >= tot) return;
    int n = (int)(idx / FDIM), ch = (int)(idx % FDIM);
    float f = SC_FEAT[idx];
    __nv_bfloat16 fh = __float2bfloat16(f);
    FBh[idx] = fh;
    FBl[idx] = __float2bfloat16(f - __bfloat162float(fh));
    int ksz = 3 + 2 * (ch >> 8);
    int p = ksz >> 1;
    float m = f;
    for (int d = -p; d <= p; ++d) {
        int nn = n + d;
        if (d != 0 && nn >= 0 && nn < N) m = fmaxf(m, SC_FEAT[(long long)nn * FDIM + ch]);
    }
    __nv_bfloat16 mh = __float2bfloat16(m);
    PBh[idx] = mh;
    PBl[idx] = __float2bfloat16(m - __bfloat162float(mh));
}

// ---------------- persistent chunked-LSTM scan v2: Whh cached in SMEM ----------------
#define WROWS 24
#define WST   196                                    // float4 row stride (padded, 196%8=4)
#define SCAN_SMEM ((WROWS * WST + 16 * 192) * 16)    // 75264 + 49152 = 124416 B

__global__ __launch_bounds__(384, 1)
void k_scan(const float* __restrict__ Whh, int N, int nChunks) {
    extern __shared__ float4 dsm[];
    float4* w4s = dsm;                // [24][196]
    float4* sh4 = dsm + WROWS * WST;  // [16][192] swizzled h tile
    float* shp = (float*)sh4;         // gate staging (aliases sh4; ordering via syncs)
    int t = threadIdx.x, b = blockIdx.x;
    int j = t & 15;
    int q = t >> 4;                   // 0..23
    int hl = q % 6, gate = q / 6;
    int h_idx = b * 6 + hl;
    int grow = gate * FDIM + h_idx;

    // load this block's 24 Whh rows into smem ONCE
    for (int idx = t; idx < WROWS * 192; idx += 384) {
        int row = idx / 192, k4 = idx - row * 192;
        int gr = (row / 6) * FDIM + b * 6 + (row % 6);
        w4s[row * WST + k4] = ((const float4*)Whh)[(size_t)gr * 192 + k4];
    }
    float c_reg = 0.f;

    for (int s = 0; s < nChunks; ++s) {
        // load previous-step h (L1-bypass for cross-SM coherence)
        const float4* src = (const float4*)(SC_H16[s & 1]);
        for (int f = t; f < 3072; f += 384) {
            float4 v = __ldcg(src + f);
            int jj = f / 192, k4 = f - jj * 192;
            sh4[jj * 192 + (k4 ^ jj)] = v;
        }
        __syncthreads();   // also orders the one-time w4s fill on s==0

        int pos = s * 16 + j;
        float pre = 0.f;
        if (pos < N) {
            const float4* wr = w4s + q * WST;
            const float4* hr = sh4 + j * 192;
            ull acc0 = 0, acc1 = 0;
#pragma unroll 8
            for (int k4 = 0; k4 < 192; ++k4) {
                float4 w = wr[k4];
                float4 h = hr[k4 ^ j];
                ull wlo, whi, hlo, hhi;
                asm("mov.b64 %0, {%1, %2};" : "=l"(wlo) : "f"(w.x), "f"(w.y));
                asm("mov.b64 %0, {%1, %2};" : "=l"(whi) : "f"(w.z), "f"(w.w));
                asm("mov.b64 %0, {%1, %2};" : "=l"(hlo) : "f"(h.x), "f"(h.y));
                asm("mov.b64 %0, {%1, %2};" : "=l"(hhi) : "f"(h.z), "f"(h.w));
                ffma2(acc0, wlo, hlo);
                ffma2(acc1, whi, hhi);
            }
            float2 s0 = up2(acc0), s1 = up2(acc1);
            pre = __ldg(&SC_G[(long long)pos * G4 + grow]) + ((s0.x + s0.y) + (s1.x + s1.y));
        }
        __syncthreads();
        shp[j * 24 + q] = pre;
        __syncthreads();

        if (q < 6 && pos < N) {
            float gi = shp[j * 24 + hl];
            float gf = shp[j * 24 + 6  + hl];
            float gg = shp[j * 24 + 12 + hl];
            float go = shp[j * 24 + 18 + hl];
            float c2 = sigm(gf) * c_reg + sigm(gi) * tanhf(gg);
            float h2 = sigm(go) * tanhf(c2);
            c_reg = c2;
            long long o = (long long)pos * FDIM + h_idx;
            SC_CS[o] = c2;
            __nv_bfloat16 hh = __float2bfloat16(h2);
            HBh[o] = hh;
            HBl[o] = __float2bfloat16(h2 - __bfloat162float(hh));
            SC_H16[(s + 1) & 1][j * FDIM + h_idx] = h2;
        }

        __threadfence();
        __syncthreads();
        if (t == 0) {
            unsigned prev = atomicAdd(&SC_ARRIVE, 1u);
            unsigned target = (unsigned)(s + 1) * gridDim.x;
            if (prev + 1 == target) {
                atomicExch(&SC_RELEASE, (unsigned)(s + 1));
            } else {
                while (*(volatile unsigned*)&SC_RELEASE < (unsigned)(s + 1)) __nanosleep(32);
            }
            __threadfence();
        }
        __syncthreads();
    }
}

// ---------------- final LSTM-cell gate fuse ----------------
__global__ void k_final(float* __restrict__ out, int N, int shift, int outOff) {
    long long idx = (long long)blockIdx.x * blockDim.x + threadIdx.x;
    long long tot = (long long)N * FDIM;
    if (idx >= tot) return;
    int n = (int)(idx / FDIM), h = (int)(idx % FDIM);
    int ns = n + shift;
    float cin = (ns >= 0 && ns < N) ? SC_CS[(long long)ns * FDIM + h] : 0.f;
    const float* g = SC_G + (long long)n * G4;
    float gi = g[h], gf = g[FDIM + h], gg = g[2 * FDIM + h], go = g[3 * FDIM + h];
    float c2 = sigm(gf) * cin + sigm(gi) * tanhf(gg);
    out[(long long)n * 1536 + outOff + h] = sigm(go) * tanhf(c2);
}

// ---------------- launch ----------------
extern "C" void kernel_launch(void* const* d_in, const int* in_sizes, int n_in,
                              void* d_out, int out_size) {
    const float* x    = (const float*)d_in[0];
    const int*   dl   = (const int*)  d_in[1];
    const float* cw0  = (const float*)d_in[2];  const float* cb0 = (const float*)d_in[3];
    const float* cw1  = (const float*)d_in[4];  const float* cb1 = (const float*)d_in[5];
    const float* cw2  = (const float*)d_in[6];  const float* cb2 = (const float*)d_in[7];
    const float* Wih  = (const float*)d_in[8];  const float* Whh  = (const float*)d_in[9];
    const float* bih  = (const float*)d_in[10]; const float* bhh  = (const float*)d_in[11];
    const float* WihR = (const float*)d_in[12]; const float* WhhR = (const float*)d_in[13];
    const float* bihR = (const float*)d_in[14]; const float* bhhR = (const float*)d_in[15];
    float* out = (float*)d_out;

    int ndocs = in_sizes[1];
    int N = out_size / 1536;
    if (N > MAXN) N = MAXN;
    int nChunks = (N + 15) / 16;

    cudaFuncSetAttribute(k_mmconv, cudaFuncAttributeMaxDynamicSharedMemorySize, SMEM_MMA);
    cudaFuncSetAttribute(k_mmgate, cudaFuncAttributeMaxDynamicSharedMemorySize, SMEM_MMA);
    cudaFuncSetAttribute(k_scan,   cudaFuncAttributeMaxDynamicSharedMemorySize, SCAN_SMEM);

    // 0: PE + posidx + conv weight transpose
    k_prep<<<(15 * 256 * D_IN + 255) / 256, 256>>>(dl, ndocs, N, cw0, cw1, cw2);
    // 1: x + PE -> XB planes
    {
        long long tot = (long long)N * KPADX;
        k_addpe_cvt<<<(int)((tot + 255) / 256), 256>>>(x, N);
    }
    // 2: all weight conversions + scan-state reset
    k_wcvt<<<(int)((4LL * G4 * FDIM + 255) / 256), 256>>>(Wih, Whh, WihR, WhhR);

    int mt = (N + 127) / 128;
    dim3 cg(mt, 2);
    // 3-5: convs
    k_mmconv<<<cg, 256, SMEM_MMA>>>(7, 8, 512, cb2, N);
    k_mmconv<<<cg, 256, SMEM_MMA>>>(5, 3, 256, cb1, N);
    k_mmconv<<<cg, 256, SMEM_MMA>>>(3, 0, 0,   cb0, N);

    // 6: pool + FB/PB planes
    {
        long long tot = (long long)N * FDIM;
        k_postconv<<<(int)((tot + 255) / 256), 256>>>(N);
    }

    dim3 gg(mt, G4 / 128);
    // 7: gx = pool @ Wih^T + b_ih + b_hh
    k_mmgate<<<gg, 256, SMEM_MMA>>>(0, 0, 0, 0, 0, bih, bhh, N);
    // 8: scan (Whh cached in smem)
    k_scan<<<128, 384, SCAN_SMEM>>>(Whh, N, nChunks);

    // 9-10: forward final cell
    k_mmgate<<<gg, 256, SMEM_MMA>>>(1, 0, 1, 1, -9, bih, bhh, N);
    {
        long long tot = (long long)N * FDIM;
        k_final<<<(int)((tot + 255) / 256), 256>>>(out, N, -9, 0);
    }
    // 11-12: reverse final cell
    k_mmgate<<<gg, 256, SMEM_MMA>>>(1, 2, 1, 3, 9, bihR, bhhR, N);
    {
        long long tot = (long long)N * FDIM;
        k_final<<<(int)((tot + 255) / 256), 256>>>(out, N, 9, 768);
    }
}

// round 9
// speedup vs baseline: 1.8382x; 1.3383x over previous
#include <cuda_runtime.h>
#include <cuda_bf16.h>
#include <math.h>
#include <stdint.h>

#define MAXN   25600
#define D_IN   1068
#define KPADX  1088
#define FDIM   768
#define G4     3072
#define NPE    200
#define MAXDOC 256

typedef unsigned long long ull;

// ---------------- scratch (static device arrays; no allocations) ----------------
__device__ float SC_PE  [NPE * D_IN];
__device__ int   SC_POS [MAXN];
__device__ float SC_WT  [15 * 256 * D_IN];            // taps: 0..2 (k3), 3..7 (k5), 8..14 (k7)
__device__ float SC_FEAT[(size_t)MAXN * FDIM];
__device__ float SC_G   [(size_t)MAXN * G4];
__device__ float SC_CS  [(size_t)MAXN * FDIM];
__device__ float SC_H16 [2][16 * FDIM];
__device__ unsigned SC_FLAG[128 * 8];                 // padded per-block barrier flags

// bf16 split planes (hi + lo), 16B aligned for cp.async
__device__ __align__(16) __nv_bfloat16 XBh[(size_t)MAXN * KPADX], XBl[(size_t)MAXN * KPADX];
__device__ __align__(16) __nv_bfloat16 WTBh[(size_t)3840 * KPADX], WTBl[(size_t)3840 * KPADX];
__device__ __align__(16) __nv_bfloat16 FBh[(size_t)MAXN * FDIM], FBl[(size_t)MAXN * FDIM];
__device__ __align__(16) __nv_bfloat16 PBh[(size_t)MAXN * FDIM], PBl[(size_t)MAXN * FDIM];
__device__ __align__(16) __nv_bfloat16 HBh[(size_t)MAXN * FDIM], HBl[(size_t)MAXN * FDIM];
__device__ __align__(16) __nv_bfloat16 WGBh[(size_t)4 * G4 * FDIM], WGBl[(size_t)4 * G4 * FDIM];

__device__ __forceinline__ float sigm(float x) { return 1.0f / (1.0f + expf(-x)); }

// ---- packed f32x2 helpers (scan) ----
__device__ __forceinline__ void ffma2(ull& d, ull a, ull b) {
    asm("fma.rn.f32x2 %0, %1, %2, %0;" : "+l"(d) : "l"(a), "l"(b));
}
__device__ __forceinline__ float2 up2(ull v) {
    float2 r; asm("mov.b64 {%0, %1}, %2;" : "=f"(r.x), "=f"(r.y) : "l"(v)); return r;
}

// ---- mma.sync / ldmatrix / cp.async (base PTX, compute_103-safe) ----
__device__ __forceinline__ uint32_t smem_u32(const void* p) {
    uint32_t a;
    asm("{ .reg .u64 t; cvta.to.shared.u64 t, %1; cvt.u32.u64 %0, t; }" : "=r"(a) : "l"(p));
    return a;
}
__device__ __forceinline__ void ldsm4(uint32_t* r, uint32_t addr) {
    asm volatile("ldmatrix.sync.aligned.m8n8.x4.shared.b16 {%0,%1,%2,%3}, [%4];"
        : "=r"(r[0]), "=r"(r[1]), "=r"(r[2]), "=r"(r[3]) : "r"(addr));
}
__device__ __forceinline__ void mma16816(float* c, const uint32_t* a, uint32_t b0, uint32_t b1) {
    asm volatile("mma.sync.aligned.m16n8k16.row.col.f32.bf16.bf16.f32 "
        "{%0,%1,%2,%3}, {%4,%5,%6,%7}, {%8,%9}, {%0,%1,%2,%3};"
        : "+f"(c[0]), "+f"(c[1]), "+f"(c[2]), "+f"(c[3])
        : "r"(a[0]), "r"(a[1]), "r"(a[2]), "r"(a[3]), "r"(b0), "r"(b1));
}
__device__ __forceinline__ void cpa16(uint32_t dst, const void* src, int valid) {
    asm volatile("cp.async.cg.shared.global [%0], [%1], 16, %2;"
        :: "r"(dst), "l"(src), "r"(valid ? 16 : 0) : "memory");
}
#define CP_COMMIT() asm volatile("cp.async.commit_group;" ::: "memory")
#define CP_WAIT1()  asm volatile("cp.async.wait_group 1;" ::: "memory")
#define CP_WAIT0()  asm volatile("cp.async.wait_group 0;" ::: "memory")

#define RS     80
#define PLANE  10240
#define BUFB   40960
#define SMEM_MMA (2 * BUFB)

// load one 128x32 bf16 plane into smem (2 chunks of 16B per thread)
__device__ __forceinline__ void ldp(uint32_t sdst, const __nv_bfloat16* src, int ldk,
                                    int rowBase, int rowLim, int kcol, int tid) {
#pragma unroll
    for (int it = 0; it < 2; ++it) {
        int ch = tid + it * 256;
        int row = ch >> 2, c = ch & 3;
        int r = rowBase + row;
        int v = (r >= 0 && r < rowLim);
        const void* s = src + ((size_t)(v ? r : 0) * ldk + kcol + c * 8);
        cpa16(sdst + row * RS + c * 16, s, v);
    }
}

// per-warp compute on one 32-K block: 3 split combos, acc[2][8][4]
__device__ __forceinline__ void wcompute(uint32_t sbuf, int lane, int wm, int wn,
                                         float acc[2][8][4]) {
    int arow = wm * 32 + (lane & 15);
    int brow = wn * 64 + (lane & 7) + ((lane >> 4) << 3);
#pragma unroll
    for (int kh = 0; kh < 2; ++kh) {
        int acol = kh * 16 + ((lane >> 4) << 3);
        int bcol = kh * 16 + (((lane >> 3) & 1) << 3);
        uint32_t ah[2][4], al[2][4];
#pragma unroll
        for (int mt = 0; mt < 2; ++mt) {
            uint32_t ad = sbuf + (arow + mt * 16) * RS + acol * 2;
            ldsm4(ah[mt], ad);
            ldsm4(al[mt], ad + PLANE);
        }
#pragma unroll
        for (int g = 0; g < 4; ++g) {
            uint32_t bh[4], bl[4];
            uint32_t bd = sbuf + 2 * PLANE + (brow + g * 16) * RS + bcol * 2;
            ldsm4(bh, bd);
            ldsm4(bl, bd + PLANE);
#pragma unroll
            for (int mt = 0; mt < 2; ++mt)
#pragma unroll
                for (int sub = 0; sub < 2; ++sub) {
                    int nt = g * 2 + sub;
                    mma16816(acc[mt][nt], ah[mt], bh[sub * 2], bh[sub * 2 + 1]);
                    mma16816(acc[mt][nt], ah[mt], bl[sub * 2], bl[sub * 2 + 1]);
                    mma16816(acc[mt][nt], al[mt], bh[sub * 2], bh[sub * 2 + 1]);
                }
        }
    }
}

// ---------------- fused prep: PE + posidx + conv weight transpose ----------------
__global__ void k_prep(const int* __restrict__ dl, int ndocs, int N,
                       const float* __restrict__ w0, const float* __restrict__ w1,
                       const float* __restrict__ w2) {
    int idx = blockIdx.x * blockDim.x + threadIdx.x;
    if (idx < NPE * D_IN) {
        int pos = idx / D_IN, ch = idx % D_IN;
        int i = ch >> 1;
        float e = (2.0f * (float)i) / (float)D_IN;
        float ang = (float)pos / powf(10000.0f, e);
        SC_PE[idx] = (ch & 1) ? cosf(ang) : sinf(ang);
    }
    const int per = 256 * D_IN;
    if (idx < 15 * per) {
        int t  = idx / per;
        int r  = idx - t * per;
        int oc = r / D_IN;
        int c  = r - oc * D_IN;
        const float* w; int ksz, tl;
        if (t < 3)      { w = w0; ksz = 3; tl = t; }
        else if (t < 8) { w = w1; ksz = 5; tl = t - 3; }
        else            { w = w2; ksz = 7; tl = t - 8; }
        SC_WT[idx] = w[((size_t)oc * D_IN + c) * ksz + tl];
    }
    if (blockIdx.x == 0) {
        __shared__ int off[MAXDOC + 1];
        if (threadIdx.x == 0) {
            int s = 0;
            for (int d = 0; d < ndocs; ++d) { off[d] = s; s += dl[d]; }
            off[ndocs] = s;
        }
        __syncthreads();
        for (int n = threadIdx.x; n < N; n += blockDim.x) {
            int lo = 0, hi = ndocs;
            while (hi - lo > 1) { int mid = (lo + hi) >> 1; if (off[mid] <= n) lo = mid; else hi = mid; }
            SC_POS[n] = n - off[lo];
        }
    }
}

// ---------------- fused: x + PE -> bf16 hi/lo planes ----------------
__global__ void k_addpe_cvt(const float* __restrict__ x, int N) {
    long long idx = (long long)blockIdx.x * blockDim.x + threadIdx.x;
    long long tot = (long long)N * KPADX;
    if (idx >= tot) return;
    int n = (int)(idx / KPADX), k = (int)(idx % KPADX);
    float v = 0.f;
    if (k < D_IN) v = x[(size_t)n * D_IN + k] + SC_PE[SC_POS[n] * D_IN + k];
    __nv_bfloat16 h = __float2bfloat16(v);
    XBh[idx] = h;
    XBl[idx] = __float2bfloat16(v - __bfloat162float(h));
}

// ---------------- fused weight conversions: WT planes + gate weight planes + reset ----------------
__global__ void k_wcvt(const float* __restrict__ s0, const float* __restrict__ s1,
                       const float* __restrict__ s2, const float* __restrict__ s3) {
    long long idx = (long long)blockIdx.x * blockDim.x + threadIdx.x;
    // conv weight planes: 3840 x KPADX
    if (idx < (long long)3840 * KPADX) {
        int r = (int)(idx / KPADX), k = (int)(idx % KPADX);
        float v = (k < D_IN) ? SC_WT[(size_t)r * D_IN + k] : 0.f;
        __nv_bfloat16 h = __float2bfloat16(v);
        WTBh[idx] = h;
        WTBl[idx] = __float2bfloat16(v - __bfloat162float(h));
    }
    // gate weight planes: 4 slots x G4 x FDIM
    const long long per = (long long)G4 * FDIM;
    if (idx < 4 * per) {
        int slot = (int)(idx / per);
        long long r = idx - (long long)slot * per;
        const float* s = (slot == 0) ? s0 : (slot == 1) ? s1 : (slot == 2) ? s2 : s3;
        float v = s[r];
        __nv_bfloat16 h = __float2bfloat16(v);
        WGBh[idx] = h;
        WGBl[idx] = __float2bfloat16(v - __bfloat162float(h));
    }
    // scan state reset
    if (idx < 128 * 8) SC_FLAG[idx] = 0u;
    if (idx < 16 * FDIM) SC_H16[0][idx] = 0.f;
}

// ---------------- mma conv ----------------
__global__ __launch_bounds__(256, 2)
void k_mmconv(int ksz, int tapBase, int ocBase, const float* __restrict__ bias, int N) {
    extern __shared__ char smem[];
    uint32_t sb = smem_u32(smem);
    int tid = threadIdx.x, lane = tid & 31, wid = tid >> 5;
    int wm = wid & 3, wn = wid >> 2;
    int m0 = blockIdx.x * 128, n0 = blockIdx.y * 128;
    int pad = ksz >> 1;
    int nblk = ksz * 34;
    float acc[2][8][4] = {};

    auto load_blk = [&](int i) {
        int buf = i & 1;
        int p = i / 34, kb = i - p * 34;
        int sh = p - pad;
        uint32_t bb = sb + buf * BUFB;
        const __nv_bfloat16* wth = WTBh + (size_t)(tapBase + p) * 256 * KPADX;
        const __nv_bfloat16* wtl = WTBl + (size_t)(tapBase + p) * 256 * KPADX;
        ldp(bb,             XBh, KPADX, m0 + sh, N,   kb * 32, tid);
        ldp(bb + PLANE,     XBl, KPADX, m0 + sh, N,   kb * 32, tid);
        ldp(bb + 2 * PLANE, wth, KPADX, n0,      256, kb * 32, tid);
        ldp(bb + 3 * PLANE, wtl, KPADX, n0,      256, kb * 32, tid);
        CP_COMMIT();
    };

    load_blk(0);
    for (int i = 0; i < nblk; ++i) {
        if (i + 1 < nblk) { load_blk(i + 1); CP_WAIT1(); } else { CP_WAIT0(); }
        __syncthreads();
        wcompute(sb + (i & 1) * BUFB, lane, wm, wn, acc);
        __syncthreads();
    }

#pragma unroll
    for (int mt = 0; mt < 2; ++mt)
#pragma unroll
        for (int nt = 0; nt < 8; ++nt) {
            int col = n0 + wn * 64 + nt * 8 + (lane & 3) * 2;
            float b0 = bias[col], b1 = bias[col + 1];
            int r0 = m0 + wm * 32 + mt * 16 + (lane >> 2);
#pragma unroll
            for (int hh = 0; hh < 2; ++hh) {
                int m = r0 + hh * 8;
                if (m < N) {
                    float v0 = acc[mt][nt][hh * 2]     + b0;
                    float v1 = acc[mt][nt][hh * 2 + 1] + b1;
                    v0 = (v0 >= 0.f) ? v0 : 0.01f * v0;
                    v1 = (v1 >= 0.f) ? v1 : 0.01f * v1;
                    SC_FEAT[(size_t)m * FDIM + ocBase + col]     = v0;
                    SC_FEAT[(size_t)m * FDIM + ocBase + col + 1] = v1;
                }
            }
        }
}

// ---------------- gate GEMM: SC_G = A1@B1^T [+ A2(shift)@B2^T] + b1 + b2 ----------------
__global__ __launch_bounds__(256, 2)
void k_mmgate(int aSel, int wSlot, int pass2, int wSlot2, int shift2,
              const float* __restrict__ b1, const float* __restrict__ b2, int N) {
    extern __shared__ char smem[];
    uint32_t sb = smem_u32(smem);
    int tid = threadIdx.x, lane = tid & 31, wid = tid >> 5;
    int wm = wid & 3, wn = wid >> 2;
    int m0 = blockIdx.x * 128, n0 = blockIdx.y * 128;
    int nblk = pass2 ? 48 : 24;
    float acc[2][8][4] = {};

    auto load_blk = [&](int i) {
        int buf = i & 1;
        int p = i / 24, kb = i - p * 24;
        const __nv_bfloat16 *ah, *al, *bh, *bl;
        int sh;
        if (p == 0) {
            ah = aSel ? FBh : PBh; al = aSel ? FBl : PBl;
            bh = WGBh + (size_t)wSlot * G4 * FDIM;
            bl = WGBl + (size_t)wSlot * G4 * FDIM;
            sh = 0;
        } else {
            ah = HBh; al = HBl;
            bh = WGBh + (size_t)wSlot2 * G4 * FDIM;
            bl = WGBl + (size_t)wSlot2 * G4 * FDIM;
            sh = shift2;
        }
        uint32_t bb = sb + buf * BUFB;
        ldp(bb,             ah, FDIM, m0 + sh, N,  kb * 32, tid);
        ldp(bb + PLANE,     al, FDIM, m0 + sh, N,  kb * 32, tid);
        ldp(bb + 2 * PLANE, bh, FDIM, n0,      G4, kb * 32, tid);
        ldp(bb + 3 * PLANE, bl, FDIM, n0,      G4, kb * 32, tid);
        CP_COMMIT();
    };

    load_blk(0);
    for (int i = 0; i < nblk; ++i) {
        if (i + 1 < nblk) { load_blk(i + 1); CP_WAIT1(); } else { CP_WAIT0(); }
        __syncthreads();
        wcompute(sb + (i & 1) * BUFB, lane, wm, wn, acc);
        __syncthreads();
    }

#pragma unroll
    for (int mt = 0; mt < 2; ++mt)
#pragma unroll
        for (int nt = 0; nt < 8; ++nt) {
            int g = n0 + wn * 64 + nt * 8 + (lane & 3) * 2;
            float bv0 = b1[g] + b2[g];
            float bv1 = b1[g + 1] + b2[g + 1];
            int r0 = m0 + wm * 32 + mt * 16 + (lane >> 2);
#pragma unroll
            for (int hh = 0; hh < 2; ++hh) {
                int m = r0 + hh * 8;
                if (m < N) {
                    SC_G[(size_t)m * G4 + g]     = acc[mt][nt][hh * 2]     + bv0;
                    SC_G[(size_t)m * G4 + g + 1] = acc[mt][nt][hh * 2 + 1] + bv1;
                }
            }
        }
}

// ---------------- fused: FEAT -> FB planes; maxpool -> PB planes ----------------
__global__ void k_postconv(int N) {
    long long idx = (long long)blockIdx.x * blockDim.x + threadIdx.x;
    long long tot = (long long)N * FDIM;
    if (idx >= tot) return;
    int n = (int)(idx / FDIM), ch = (int)(idx % FDIM);
    float f = SC_FEAT[idx];
    __nv_bfloat16 fh = __float2bfloat16(f);
    FBh[idx] = fh;
    FBl[idx] = __float2bfloat16(f - __bfloat162float(fh));
    int ksz = 3 + 2 * (ch >> 8);
    int p = ksz >> 1;
    float m = f;
    for (int d = -p; d <= p; ++d) {
        int nn = n + d;
        if (d != 0 && nn >= 0 && nn < N) m = fmaxf(m, SC_FEAT[(long long)nn * FDIM + ch]);
    }
    __nv_bfloat16 mh = __float2bfloat16(m);
    PBh[idx] = mh;
    PBl[idx] = __float2bfloat16(m - __bfloat162float(mh));
}

// ---------------- persistent chunked-LSTM scan v3: h-reuse + flag barrier ----------------
// 128 blocks x 384 threads. thread = (j = t&15, qt = (t>>4)%6, ks = t/96).
// Each thread computes 4 gate rows (qt + 6g) over k-chunk [ks*192, ks*192+192).
#define WROWS 24
#define WST   196                                    // float4 row stride (padded)
#define SCAN_SMEM ((WROWS * WST + 16 * 192) * 16)    // 75264 + 49152 = 124416 B

__global__ __launch_bounds__(384, 1)
void k_scan(const float* __restrict__ Whh, int N, int nChunks) {
    extern __shared__ float4 dsm[];
    float4* w4s = dsm;                // [24][196]
    float4* sh4 = dsm + WROWS * WST;  // [16][192] swizzled h tile
    float* shp = (float*)sh4;         // partial staging (aliases h tile; ordered by syncs)
    int t = threadIdx.x, b = blockIdx.x;
    int j = t & 15;
    int qt = (t >> 4) % 6;
    int ks = t / 96;                  // 0..3
    int kbase = ks * 48;
    int hl = t >> 4;                  // valid for cell threads (t < 96)
    int h_idx = b * 6 + hl;

    // load this block's 24 Whh rows into smem ONCE
    for (int idx = t; idx < WROWS * 192; idx += 384) {
        int row = idx / 192, k4 = idx - row * 192;
        int gr = (row / 6) * FDIM + b * 6 + (row % 6);
        w4s[row * WST + k4] = ((const float4*)Whh)[(size_t)gr * 192 + k4];
    }
    float c_reg = 0.f;

    for (int s = 0; s < nChunks; ++s) {
        int pos = s * 16 + j;
        // G prefetch for cell threads — independent of the barrier
        float gpre[4] = {0.f, 0.f, 0.f, 0.f};
        if (t < 96 && pos < N) {
#pragma unroll
            for (int g = 0; g < 4; ++g)
                gpre[g] = __ldg(&SC_G[(size_t)pos * G4 + g * FDIM + h_idx]);
        }
        // flag barrier: wait until all 128 blocks have signalled step s
        if (s > 0 && t < 128) {
            while (*(volatile unsigned*)&SC_FLAG[t * 8] < (unsigned)s) __nanosleep(32);
        }
        __syncthreads();
        __threadfence();

        // load previous-step h (L2-coherent) into swizzled smem tile
        const float4* src = (const float4*)(SC_H16[s & 1]);
        for (int f = t; f < 3072; f += 384) {
            float4 v = __ldcg(src + f);
            int jj = f / 192, k4 = f - jj * 192;
            sh4[jj * 192 + (k4 ^ jj)] = v;
        }
        __syncthreads();   // also orders the one-time w4s fill (s==0)

        // partial dot products: 4 gate rows x 192-float k-chunk, h loaded once per k4
        ull acc[4][2] = {{0, 0}, {0, 0}, {0, 0}, {0, 0}};
        {
            const float4* hr = sh4 + j * 192;
#pragma unroll 4
            for (int kk = 0; kk < 48; ++kk) {
                int k4 = kbase + kk;
                ulonglong2 hv = *(const ulonglong2*)(hr + (k4 ^ j));
#pragma unroll
                for (int g = 0; g < 4; ++g) {
                    ulonglong2 wv = *(const ulonglong2*)(w4s + (qt + 6 * g) * WST + k4);
                    ffma2(acc[g][0], wv.x, hv.x);
                    ffma2(acc[g][1], wv.y, hv.y);
                }
            }
        }
        __syncthreads();   // all h-tile reads done before aliased partial writes
#pragma unroll
        for (int g = 0; g < 4; ++g) {
            float2 a0 = up2(acc[g][0]), a1 = up2(acc[g][1]);
            shp[((ks * 4 + g) * 6 + qt) * 16 + j] = (a0.x + a0.y) + (a1.x + a1.y);
        }
        __syncthreads();

        // cell update: 96 threads (j, hl)
        if (t < 96 && pos < N) {
            float pre[4];
#pragma unroll
            for (int g = 0; g < 4; ++g) {
                float sgd = gpre[g];
#pragma unroll
                for (int kss = 0; kss < 4; ++kss)
                    sgd += shp[((kss * 4 + g) * 6 + hl) * 16 + j];
                pre[g] = sgd;
            }
            float c2 = sigm(pre[1]) * c_reg + sigm(pre[0]) * tanhf(pre[2]);
            float h2 = sigm(pre[3]) * tanhf(c2);
            c_reg = c2;
            size_t o = (size_t)pos * FDIM + h_idx;
            SC_CS[o] = c2;
            __nv_bfloat16 hh = __float2bfloat16(h2);
            HBh[o] = hh;
            HBl[o] = __float2bfloat16(h2 - __bfloat162float(hh));
            SC_H16[(s + 1) & 1][j * FDIM + h_idx] = h2;
        }

        __threadfence();
        __syncthreads();
        if (t == 0) atomicExch(&SC_FLAG[b * 8], (unsigned)(s + 1));
    }
}

// ---------------- final LSTM-cell gate fuse ----------------
__global__ void k_final(float* __restrict__ out, int N, int shift, int outOff) {
    long long idx = (long long)blockIdx.x * blockDim.x + threadIdx.x;
    long long tot = (long long)N * FDIM;
    if (idx >= tot) return;
    int n = (int)(idx / FDIM), h = (int)(idx % FDIM);
    int ns = n + shift;
    float cin = (ns >= 0 && ns < N) ? SC_CS[(long long)ns * FDIM + h] : 0.f;
    const float* g = SC_G + (long long)n * G4;
    float gi = g[h], gf = g[FDIM + h], gg = g[2 * FDIM + h], go = g[3 * FDIM + h];
    float c2 = sigm(gf) * cin + sigm(gi) * tanhf(gg);
    out[(long long)n * 1536 + outOff + h] = sigm(go) * tanhf(c2);
}

// ---------------- launch ----------------
extern "C" void kernel_launch(void* const* d_in, const int* in_sizes, int n_in,
                              void* d_out, int out_size) {
    const float* x    = (const float*)d_in[0];
    const int*   dl   = (const int*)  d_in[1];
    const float* cw0  = (const float*)d_in[2];  const float* cb0 = (const float*)d_in[3];
    const float* cw1  = (const float*)d_in[4];  const float* cb1 = (const float*)d_in[5];
    const float* cw2  = (const float*)d_in[6];  const float* cb2 = (const float*)d_in[7];
    const float* Wih  = (const float*)d_in[8];  const float* Whh  = (const float*)d_in[9];
    const float* bih  = (const float*)d_in[10]; const float* bhh  = (const float*)d_in[11];
    const float* WihR = (const float*)d_in[12]; const float* WhhR = (const float*)d_in[13];
    const float* bihR = (const float*)d_in[14]; const float* bhhR = (const float*)d_in[15];
    float* out = (float*)d_out;

    int ndocs = in_sizes[1];
    int N = out_size / 1536;
    if (N > MAXN) N = MAXN;
    int nChunks = (N + 15) / 16;

    cudaFuncSetAttribute(k_mmconv, cudaFuncAttributeMaxDynamicSharedMemorySize, SMEM_MMA);
    cudaFuncSetAttribute(k_mmgate, cudaFuncAttributeMaxDynamicSharedMemorySize, SMEM_MMA);
    cudaFuncSetAttribute(k_scan,   cudaFuncAttributeMaxDynamicSharedMemorySize, SCAN_SMEM);

    // 0: PE + posidx + conv weight transpose
    k_prep<<<(15 * 256 * D_IN + 255) / 256, 256>>>(dl, ndocs, N, cw0, cw1, cw2);
    // 1: x + PE -> XB planes
    {
        long long tot = (long long)N * KPADX;
        k_addpe_cvt<<<(int)((tot + 255) / 256), 256>>>(x, N);
    }
    // 2: all weight conversions + scan-state reset
    k_wcvt<<<(int)((4LL * G4 * FDIM + 255) / 256), 256>>>(Wih, Whh, WihR, WhhR);

    int mt = (N + 127) / 128;
    dim3 cg(mt, 2);
    // 3-5: convs
    k_mmconv<<<cg, 256, SMEM_MMA>>>(7, 8, 512, cb2, N);
    k_mmconv<<<cg, 256, SMEM_MMA>>>(5, 3, 256, cb1, N);
    k_mmconv<<<cg, 256, SMEM_MMA>>>(3, 0, 0,   cb0, N);

    // 6: pool + FB/PB planes
    {
        long long tot = (long long)N * FDIM;
        k_postconv<<<(int)((tot + 255) / 256), 256>>>(N);
    }

    dim3 gg(mt, G4 / 128);
    // 7: gx = pool @ Wih^T + b_ih + b_hh
    k_mmgate<<<gg, 256, SMEM_MMA>>>(0, 0, 0, 0, 0, bih, bhh, N);
    // 8: scan (h-reuse + flag barrier)
    k_scan<<<128, 384, SCAN_SMEM>>>(Whh, N, nChunks);

    // 9-10: forward final cell
    k_mmgate<<<gg, 256, SMEM_MMA>>>(1, 0, 1, 1, -9, bih, bhh, N);
    {
        long long tot = (long long)N * FDIM;
        k_final<<<(int)((tot + 255) / 256), 256>>>(out, N, -9, 0);
    }
    // 11-12: reverse final cell
    k_mmgate<<<gg, 256, SMEM_MMA>>>(1, 2, 1, 3, 9, bihR, bhhR, N);
    {
        long long tot = (long long)N * FDIM;
        k_final<<<(int)((tot + 255) / 256), 256>>>(out, N, 9, 768);
    }
}